// round 6
// baseline (speedup 1.0000x reference)
#include <cuda_runtime.h>
#include <cstdint>

// ---- problem constants ----
#define BSZ 8
#define SEQLEN 16
#define DIM 4096
#define NH 32
#define NKV 8
#define HD 128
#define CACHE 4096
#define M_TOT 128
#define QKV_N 6144
#define CACHE_PER_B 4194304L // 4096*8*128
#define CK_OFF 524288L
#define CV_OFF 34078720L
#define INV_SQRT_HD 0.08838834764831845f
#define TSPLIT 8
#define NC 16              // chunks of 32 rows per CTA (512 / 32)

// flash smem layout (u32 words)
#define QFRAG_W 8192       // [4 wm][16 ks][32 lane][4]
#define KS_W (32 * 132)
#define VS_W (32 * 136)
#define PFRAG_W 2048       // [4 wm][4 kb][32 lane][4]
#define FLASH_SMEM_BYTES ((QFRAG_W + KS_W + VS_W + PFRAG_W) * 4)

// ---- scratch ----
__device__ float g_qkv_part[4][M_TOT * QKV_N];
__device__ float g_xq[64 * 64 * 128];              // [pair][row][d], pre-scaled by 1/sqrt(hd)
__device__ float g_opart[64 * TSPLIT * 64 * 128];  // flash partial O
__device__ float2 g_ml[64 * TSPLIT * 64];          // flash partial (m, l)
__device__ float g_attn[M_TOT * 4096];             // [b*16+q][h*128+d]
__device__ float g_out_part[4][M_TOT * DIM];

// ---- helpers ----
__device__ __forceinline__ uint32_t f2tf(float f) {
    uint32_t u;
    asm("cvt.rna.tf32.f32 %0, %1;" : "=r"(u) : "f"(f));
    return u;
}

__device__ __forceinline__ void mma_tf32(float (&d)[4], const uint32_t (&a)[4],
                                         const uint32_t (&b)[2]) {
    asm volatile(
        "mma.sync.aligned.m16n8k8.row.col.f32.tf32.tf32.f32 "
        "{%0,%1,%2,%3}, {%4,%5,%6,%7}, {%8,%9}, {%0,%1,%2,%3};\n"
        : "+f"(d[0]), "+f"(d[1]), "+f"(d[2]), "+f"(d[3])
        : "r"(a[0]), "r"(a[1]), "r"(a[2]), "r"(a[3]), "r"(b[0]), "r"(b[1]));
}

__device__ __forceinline__ void cp16(uint32_t s, const void* g) {
    asm volatile("cp.async.cg.shared.global [%0], [%1], 16;\n" ::"r"(s), "l"(g));
}
__device__ __forceinline__ void cp_commit() {
    asm volatile("cp.async.commit_group;\n");
}

// ================= cache shift =================
__global__ void shift_caches(const float4* __restrict__ ck,
                             const float4* __restrict__ cv,
                             float4* __restrict__ out) {
    long i = (long)blockIdx.x * 256 + threadIdx.x;
    const long PER = 8L * 4080 * 256;
    if (i < PER) {
        long b = i / (4080L * 256), r = i - b * (4080L * 256);
        out[CK_OFF / 4 + b * 1048576 + r] = ck[b * 1048576 + 4096 + r];
    } else if (i < 2 * PER) {
        long j = i - PER;
        long b = j / (4080L * 256), r = j - b * (4080L * 256);
        out[CV_OFF / 4 + b * 1048576 + r] = cv[b * 1048576 + 4096 + r];
    }
}

// ================= generic tf32 mma core: C += A(row,[M][K]) * B(row,[N][K])^T ==========
template <int MF>
__device__ __forceinline__ void gemm_abt_core(const float* __restrict__ A, long lda,
                                              const float* __restrict__ B, long ldb,
                                              int ktiles, uint32_t* As, uint32_t* Bs,
                                              float (&acc)[MF][4][4]) {
    const int tid = threadIdx.x;
    const int lane = tid & 31, wid = tid >> 5;
    const int wm = wid >> 2, wn = wid & 3;
    const int g = lane >> 2, tig = lane & 3;

    for (int t = 0; t < ktiles; t++) {
        const float* Ak = A + t * 16;
        const float* Bk = B + t * 16;
#pragma unroll
        for (int i = 0; i < MF / 2; i++) {
            int v = tid + i * 256;
            int r = v >> 2, c4 = v & 3;
            float4 x = *(const float4*)(Ak + (long)r * lda + c4 * 4);
            uint4 y = make_uint4(f2tf(x.x), f2tf(x.y), f2tf(x.z), f2tf(x.w));
            *(uint4*)(As + r * 20 + c4 * 4) = y;
        }
#pragma unroll
        for (int i = 0; i < 2; i++) {
            int v = tid + i * 256;
            int r = v >> 2, c4 = v & 3;
            float4 x = *(const float4*)(Bk + (long)r * ldb + c4 * 4);
            uint4 y = make_uint4(f2tf(x.x), f2tf(x.y), f2tf(x.z), f2tf(x.w));
            *(uint4*)(Bs + r * 20 + c4 * 4) = y;
        }
        __syncthreads();
#pragma unroll
        for (int ks = 0; ks < 16; ks += 8) {
            uint32_t a[MF][4], b[4][2];
#pragma unroll
            for (int mf = 0; mf < MF; mf++) {
                int m = wm * (MF * 16) + mf * 16;
                a[mf][0] = As[(m + g) * 20 + ks + tig];
                a[mf][1] = As[(m + g + 8) * 20 + ks + tig];
                a[mf][2] = As[(m + g) * 20 + ks + tig + 4];
                a[mf][3] = As[(m + g + 8) * 20 + ks + tig + 4];
            }
#pragma unroll
            for (int nf = 0; nf < 4; nf++) {
                int n = wn * 32 + nf * 8 + g;
                b[nf][0] = Bs[n * 20 + ks + tig];
                b[nf][1] = Bs[n * 20 + ks + tig + 4];
            }
#pragma unroll
            for (int mf = 0; mf < MF; mf++)
#pragma unroll
                for (int nf = 0; nf < 4; nf++) mma_tf32(acc[mf][nf], a[mf], b[nf]);
        }
        __syncthreads();
    }
}

template <int MF>
__device__ __forceinline__ void store_acc(float* __restrict__ C, long ldc,
                                          float (&acc)[MF][4][4]) {
    const int tid = threadIdx.x;
    const int lane = tid & 31, wid = tid >> 5;
    const int wm = wid >> 2, wn = wid & 3;
    const int g = lane >> 2, tig = lane & 3;
#pragma unroll
    for (int mf = 0; mf < MF; mf++) {
        int m = wm * (MF * 16) + mf * 16 + g;
#pragma unroll
        for (int nf = 0; nf < 4; nf++) {
            int n = wn * 32 + nf * 8 + 2 * tig;
            *(float2*)(C + (long)m * ldc + n) = make_float2(acc[mf][nf][0], acc[mf][nf][1]);
            *(float2*)(C + (long)(m + 8) * ldc + n) = make_float2(acc[mf][nf][2], acc[mf][nf][3]);
        }
    }
}

// ================= QKV projection (split-K=4) =================
__global__ void qkv_gemm_t(const float* __restrict__ X, const float* __restrict__ wq,
                           const float* __restrict__ wk, const float* __restrict__ wv) {
    __shared__ uint32_t As[128 * 20], Bs[128 * 20];
    int n0 = blockIdx.x * 128, split = blockIdx.y;
    const float* W;
    int nl;
    if (n0 < 4096) { W = wq; nl = n0; }
    else if (n0 < 5120) { W = wk; nl = n0 - 4096; }
    else { W = wv; nl = n0 - 5120; }
    float acc[4][4][4] = {};
    gemm_abt_core<4>(X + split * 1024, 4096, W + (long)nl * 4096 + split * 1024, 4096, 64,
                     As, Bs, acc);
    store_acc<4>(g_qkv_part[split] + n0, QKV_N, acc);
}

// ================= RoPE + split reduce + scatter K/V =================
__global__ void rope_scatter(const float* __restrict__ freqs, float* __restrict__ out) {
    int m = blockIdx.x;
    int b = m >> 4, s = m & 15;
    long base = (long)m * QKV_N;
#pragma unroll 1
    for (int p = threadIdx.x; p < 2048; p += 256) {
        int h = p >> 6, i = p & 63;
        float re = g_qkv_part[0][base + 2 * p] + g_qkv_part[1][base + 2 * p] +
                   g_qkv_part[2][base + 2 * p] + g_qkv_part[3][base + 2 * p];
        float im = g_qkv_part[0][base + 2 * p + 1] + g_qkv_part[1][base + 2 * p + 1] +
                   g_qkv_part[2][base + 2 * p + 1] + g_qkv_part[3][base + 2 * p + 1];
        float c = freqs[(s * 64 + i) * 2], sn = freqs[(s * 64 + i) * 2 + 1];
        long d = ((long)(b * 32 + h) * 16 + s) * 128 + 2 * i;
        g_xq[d] = (re * c - im * sn) * INV_SQRT_HD;      // fold 1/sqrt(hd)
        g_xq[d + 1] = (re * sn + im * c) * INV_SQRT_HD;
    }
    float* ck = out + CK_OFF + (long)b * CACHE_PER_B + (long)(4080 + s) * 1024;
#pragma unroll 1
    for (int p = threadIdx.x; p < 512; p += 256) {
        int i = p & 63;
        long o = base + 4096 + 2 * p;
        float re = g_qkv_part[0][o] + g_qkv_part[1][o] + g_qkv_part[2][o] + g_qkv_part[3][o];
        float im = g_qkv_part[0][o + 1] + g_qkv_part[1][o + 1] + g_qkv_part[2][o + 1] +
                   g_qkv_part[3][o + 1];
        float c = freqs[(s * 64 + i) * 2], sn = freqs[(s * 64 + i) * 2 + 1];
        ck[2 * p] = re * c - im * sn;
        ck[2 * p + 1] = re * sn + im * c;
    }
    float* cv = out + CV_OFF + (long)b * CACHE_PER_B + (long)(4080 + s) * 1024;
#pragma unroll 1
    for (int j = threadIdx.x; j < 1024; j += 256) {
        long o = base + 5120 + j;
        cv[j] = g_qkv_part[0][o] + g_qkv_part[1][o] + g_qkv_part[2][o] + g_qkv_part[3][o];
    }
}

// ================= pipelined flash attention =================
// grid (64 pairs, TSPLIT). 256 threads = 8 warps (wm 0..3 rows x16, wn 0..1).
// Chunk = 32 t-rows. cp.async K/V raw fp32; cvt at frag load.
__global__ void __launch_bounds__(256, 2)
flash_attn(const float* __restrict__ ck, const float* __restrict__ cv,
           const float* __restrict__ mask) {
    extern __shared__ uint32_t sh[];
    uint32_t* Qf = sh;                               // frag dump [wm][ks][lane][4]
    float* KsF = (float*)(sh + QFRAG_W);             // raw K, stride 132
    float* VsF = (float*)(sh + QFRAG_W + KS_W);      // raw V, stride 136
    uint32_t* Pf = sh + QFRAG_W + KS_W + VS_W;       // P frag dump [wm][kb][lane][4]
    __shared__ float redm[2][64], redl[2][64];

    int pair = blockIdx.x, ts = blockIdx.y;
    int b = pair >> 3, kv = pair & 7;
    int tid = threadIdx.x, lane = tid & 31, w = tid >> 5;
    int wm = w >> 1, wn = w & 1;
    int g = lane >> 2, tig = lane & 3;
    int row0 = wm * 16;

    const float* Kbase = ck + (long)b * CACHE_PER_B + kv * 128;
    const float* Vbase = cv + (long)b * CACHE_PER_B + kv * 128;
    uint32_t ks_s = (uint32_t)__cvta_generic_to_shared(KsF);
    uint32_t vs_s = (uint32_t)__cvta_generic_to_shared(VsF);
    int t00 = ts * 512;

    // prologue: issue K0, V0
#pragma unroll
    for (int i = 0; i < 4; i++) {
        int bid = i * 256 + tid, r = bid >> 5, bl = bid & 31;
        cp16(ks_s + (r * 132 + bl * 4) * 4, Kbase + (long)(t00 + r) * 1024 + bl * 4);
    }
    cp_commit();
#pragma unroll
    for (int i = 0; i < 4; i++) {
        int bid = i * 256 + tid, r = bid >> 5, bl = bid & 31;
        cp16(vs_s + (r * 136 + bl * 4) * 4, Vbase + (long)(t00 + r) * 1024 + bl * 4);
    }
    cp_commit();

    // Q fragment gather (overlaps the async loads); wn halves the ks range
    const float* Q = g_xq + (long)pair * 8192;
#pragma unroll
    for (int kk = 0; kk < 8; kk++) {
        int ks = wn * 8 + kk;
        uint32_t v0 = f2tf(Q[(row0 + g) * 128 + ks * 8 + tig]);
        uint32_t v1 = f2tf(Q[(row0 + g + 8) * 128 + ks * 8 + tig]);
        uint32_t v2 = f2tf(Q[(row0 + g) * 128 + ks * 8 + tig + 4]);
        uint32_t v3 = f2tf(Q[(row0 + g + 8) * 128 + ks * 8 + tig + 4]);
        *(uint4*)(Qf + ((wm * 16 + ks) * 32 + lane) * 4) = make_uint4(v0, v1, v2, v3);
    }

    float o[8][4] = {};
    float m_lo = -1e30f, m_hi = -1e30f, l_lo = 0.f, l_hi = 0.f;

    asm volatile("cp.async.wait_group 1;\n");  // K0 ready
    __syncthreads();

    for (int c = 0; c < NC; c++) {
        int t0 = t00 + c * 32;
        // ---- S = Q K^T : 16 rows x 16 cols per warp ----
        float s[2][4] = {};
#pragma unroll
        for (int ks2 = 0; ks2 < 16; ks2++) {
            uint4 av = *(uint4*)(Qf + ((wm * 16 + ks2) * 32 + lane) * 4);
            uint32_t a[4] = {av.x, av.y, av.z, av.w};
#pragma unroll
            for (int nf = 0; nf < 2; nf++) {
                int n = wn * 16 + nf * 8 + g;
                uint32_t b2[2];
                b2[0] = f2tf(KsF[n * 132 + ks2 * 8 + tig]);
                b2[1] = f2tf(KsF[n * 132 + ks2 * 8 + tig + 4]);
                mma_tf32(s[nf], a, b2);
            }
        }
        // ---- mask + warp-local max ----
        float mx_lo = -1e30f, mx_hi = -1e30f;
#pragma unroll
        for (int nf = 0; nf < 2; nf++) {
            int t = t0 + wn * 16 + nf * 8 + 2 * tig;
            float2 mk0 = *(const float2*)&mask[g * 4096 + t];
            float2 mk1 = *(const float2*)&mask[(g + 8) * 4096 + t];
            s[nf][0] += mk0.x; s[nf][1] += mk0.y;
            s[nf][2] += mk1.x; s[nf][3] += mk1.y;
            mx_lo = fmaxf(mx_lo, fmaxf(s[nf][0], s[nf][1]));
            mx_hi = fmaxf(mx_hi, fmaxf(s[nf][2], s[nf][3]));
        }
        mx_lo = fmaxf(mx_lo, __shfl_xor_sync(0xffffffffu, mx_lo, 1));
        mx_lo = fmaxf(mx_lo, __shfl_xor_sync(0xffffffffu, mx_lo, 2));
        mx_hi = fmaxf(mx_hi, __shfl_xor_sync(0xffffffffu, mx_hi, 1));
        mx_hi = fmaxf(mx_hi, __shfl_xor_sync(0xffffffffu, mx_hi, 2));
        if (tig == 0) { redm[wn][row0 + g] = mx_lo; redm[wn][row0 + g + 8] = mx_hi; }
        __syncthreads();  // (a) Ks free + redm visible

        if (c + 1 < NC) {  // prefetch K_{c+1} (covered by softmax + PV)
#pragma unroll
            for (int i = 0; i < 4; i++) {
                int bid = i * 256 + tid, r = bid >> 5, bl = bid & 31;
                cp16(ks_s + (r * 132 + bl * 4) * 4,
                     Kbase + (long)(t0 + 32 + r) * 1024 + bl * 4);
            }
            cp_commit();
        }

        mx_lo = fmaxf(mx_lo, redm[1 - wn][row0 + g]);
        mx_hi = fmaxf(mx_hi, redm[1 - wn][row0 + g + 8]);
        float mn_lo = fmaxf(m_lo, mx_lo), mn_hi = fmaxf(m_hi, mx_hi);
        float al_lo = __expf(m_lo - mn_lo), al_hi = __expf(m_hi - mn_hi);
        m_lo = mn_lo; m_hi = mn_hi;
        float sum_lo = 0.f, sum_hi = 0.f;
#pragma unroll
        for (int nf = 0; nf < 2; nf++) {
            s[nf][0] = __expf(s[nf][0] - m_lo);
            s[nf][1] = __expf(s[nf][1] - m_lo);
            s[nf][2] = __expf(s[nf][2] - m_hi);
            s[nf][3] = __expf(s[nf][3] - m_hi);
            sum_lo += s[nf][0] + s[nf][1];
            sum_hi += s[nf][2] + s[nf][3];
        }
        // write P fragments (scatter into frag-dump layout)
#pragma unroll
        for (int nf = 0; nf < 2; nf++) {
            int kb = wn * 2 + nf;
#pragma unroll
            for (int cc = 0; cc < 4; cc++) {
                int rho = cc >> 1, e = cc & 1;
                int j = 2 * tig + e;
                int tp = j & 3, kap = j >> 2;
                Pf[((wm * 4 + kb) * 32 + g * 4 + tp) * 4 + kap * 2 + rho] = f2tf(s[nf][cc]);
            }
        }
        sum_lo += __shfl_xor_sync(0xffffffffu, sum_lo, 1);
        sum_lo += __shfl_xor_sync(0xffffffffu, sum_lo, 2);
        sum_hi += __shfl_xor_sync(0xffffffffu, sum_hi, 1);
        sum_hi += __shfl_xor_sync(0xffffffffu, sum_hi, 2);
        if (tig == 0) { redl[wn][row0 + g] = sum_lo; redl[wn][row0 + g + 8] = sum_hi; }
        if (c + 1 < NC) asm volatile("cp.async.wait_group 1;\n");  // V_c ready
        else            asm volatile("cp.async.wait_group 0;\n");
        __syncthreads();  // (b) redl + Pf + Vs visible

        sum_lo += redl[1 - wn][row0 + g];
        sum_hi += redl[1 - wn][row0 + g + 8];
        l_lo = l_lo * al_lo + sum_lo;
        l_hi = l_hi * al_hi + sum_hi;
#pragma unroll
        for (int nf = 0; nf < 8; nf++) {
            o[nf][0] *= al_lo; o[nf][1] *= al_lo;
            o[nf][2] *= al_hi; o[nf][3] *= al_hi;
        }
        // ---- O += P V : 16 rows x 64 d per warp ----
#pragma unroll
        for (int kb = 0; kb < 4; kb++) {
            uint4 av = *(uint4*)(Pf + ((wm * 4 + kb) * 32 + lane) * 4);
            uint32_t a[4] = {av.x, av.y, av.z, av.w};
#pragma unroll
            for (int nf = 0; nf < 8; nf++) {
                int n = wn * 64 + nf * 8 + g;
                uint32_t b2[2];
                b2[0] = f2tf(VsF[(kb * 8 + tig) * 136 + n]);
                b2[1] = f2tf(VsF[(kb * 8 + tig + 4) * 136 + n]);
                mma_tf32(o[nf], a, b2);
            }
        }
        __syncthreads();  // (c) Vs free

        if (c + 1 < NC) {  // prefetch V_{c+1} (covered by next S), then wait K_{c+1}
#pragma unroll
            for (int i = 0; i < 4; i++) {
                int bid = i * 256 + tid, r = bid >> 5, bl = bid & 31;
                cp16(vs_s + (r * 136 + bl * 4) * 4,
                     Vbase + (long)(t0 + 32 + r) * 1024 + bl * 4);
            }
            cp_commit();
            asm volatile("cp.async.wait_group 1;\n");  // K_{c+1} ready
            __syncthreads();  // (d) Ks visible
        }
    }

    // epilogue: unnormalized O + (m,l)
    float* Op = g_opart + ((long)(pair * TSPLIT + ts) * 64 + row0) * 128;
#pragma unroll
    for (int nf = 0; nf < 8; nf++) {
        int d = wn * 64 + nf * 8 + 2 * tig;
        *(float2*)&Op[g * 128 + d] = make_float2(o[nf][0], o[nf][1]);
        *(float2*)&Op[(g + 8) * 128 + d] = make_float2(o[nf][2], o[nf][3]);
    }
    if (tig == 0 && wn == 0) {
        g_ml[(pair * TSPLIT + ts) * 64 + row0 + g] = make_float2(m_lo, l_lo);
        g_ml[(pair * TSPLIT + ts) * 64 + row0 + g + 8] = make_float2(m_hi, l_hi);
    }
}

// ================= flash combine (LSE merge of TSPLIT splits) =================
__global__ void flash_combine() {
    int row = blockIdx.x;  // pair*64 + r
    int pair = row >> 6, r = row & 63;
    int b = pair >> 3, kv = pair & 7;
    int hl = r >> 4, q = r & 15;
    int d = threadIdx.x;
    float2 ml[TSPLIT];
    float M = -1e30f;
#pragma unroll
    for (int ts = 0; ts < TSPLIT; ts++) {
        ml[ts] = g_ml[(pair * TSPLIT + ts) * 64 + r];
        M = fmaxf(M, ml[ts].x);
    }
    float L = 0.f, acc = 0.f;
#pragma unroll
    for (int ts = 0; ts < TSPLIT; ts++) {
        float wgt = __expf(ml[ts].x - M);
        L += ml[ts].y * wgt;
        acc += wgt * g_opart[((long)(pair * TSPLIT + ts) * 64 + r) * 128 + d];
    }
    g_attn[((long)(b * 16 + q) * 4096) + (kv * 4 + hl) * 128 + d] = acc / L;
}

// ================= out = attn @ wo^T (split-K=4) =================
__global__ void out_gemm_t(const float* __restrict__ wo) {
    __shared__ uint32_t As[128 * 20], Bs[128 * 20];
    int n0 = blockIdx.x * 128, split = blockIdx.y;
    float acc[4][4][4] = {};
    gemm_abt_core<4>(g_attn + split * 1024, 4096, wo + (long)n0 * 4096 + split * 1024, 4096,
                     64, As, Bs, acc);
    store_acc<4>(g_out_part[split] + n0, 4096, acc);
}

__global__ void out_reduce(float* __restrict__ out) {
    long idx = (long)blockIdx.x * 256 + threadIdx.x;
    float4 p0 = ((const float4*)g_out_part[0])[idx];
    float4 p1 = ((const float4*)g_out_part[1])[idx];
    float4 p2 = ((const float4*)g_out_part[2])[idx];
    float4 p3 = ((const float4*)g_out_part[3])[idx];
    ((float4*)out)[idx] = make_float4(p0.x + p1.x + p2.x + p3.x, p0.y + p1.y + p2.y + p3.y,
                                      p0.z + p1.z + p2.z + p3.z, p0.w + p1.w + p2.w + p3.w);
}

// ================= launch =================
extern "C" void kernel_launch(void* const* d_in, const int* in_sizes, int n_in,
                              void* d_out, int out_size) {
    const float* x     = (const float*)d_in[0];
    const float* mask  = (const float*)d_in[1];
    const float* freqs = (const float*)d_in[2];
    const float* ck    = (const float*)d_in[3];
    const float* cv    = (const float*)d_in[4];
    const float* wq    = (const float*)d_in[5];
    const float* wk    = (const float*)d_in[6];
    const float* wv    = (const float*)d_in[7];
    const float* wo    = (const float*)d_in[8];
    float* out = (float*)d_out;

    static int smem_set = 0;
    if (!smem_set) {
        cudaFuncSetAttribute(flash_attn, cudaFuncAttributeMaxDynamicSharedMemorySize,
                             FLASH_SMEM_BYTES);
        smem_set = 1;
    }

    shift_caches<<<65280, 256>>>((const float4*)ck, (const float4*)cv, (float4*)out);
    qkv_gemm_t<<<dim3(48, 4), 256>>>(x, wq, wk, wv);
    rope_scatter<<<128, 256>>>(freqs, out);
    flash_attn<<<dim3(64, TSPLIT), 256, FLASH_SMEM_BYTES>>>(out + CK_OFF, out + CV_OFF, mask);
    flash_combine<<<4096, 128>>>();
    out_gemm_t<<<dim3(32, 4), 256>>>(wo);
    out_reduce<<<512, 256>>>(out);
}

// round 8
// speedup vs baseline: 1.4393x; 1.4393x over previous
#include <cuda_runtime.h>
#include <cstdint>

// ---- problem constants ----
#define BSZ 8
#define SEQLEN 16
#define DIM 4096
#define NH 32
#define NKV 8
#define HD 128
#define CACHE 4096
#define M_TOT 128
#define QKV_N 6144
#define CACHE_PER_B 4194304L // 4096*8*128
#define CK_OFF 524288L
#define CV_OFF 34078720L
#define INV_SQRT_HD 0.08838834764831845f

// ---- scratch ----
__device__ float g_qkv_part[4][M_TOT * QKV_N];
__device__ float g_xq[64 * 64 * 128];            // [pair*64+row][d], pre-scaled 1/sqrt(hd)
__device__ float g_knew[BSZ * 16 * 1024];        // [b*16+s][kv*128+d] rope'd new K
__device__ float g_vnew[BSZ * 16 * 1024];        // new V
__device__ float g_scores[4096 * 4096];          // [pair*64+r][t]  (64MB, L2-resident)
__device__ float g_attn_part[4][64 * 64 * 128];
__device__ float g_attn[M_TOT * 4096];
__device__ float g_out_part[4][M_TOT * DIM];

// ---- helpers ----
__device__ __forceinline__ uint32_t f2tf(float f) {
    uint32_t u;
    asm("cvt.rna.tf32.f32 %0, %1;" : "=r"(u) : "f"(f));
    return u;
}
__device__ __forceinline__ void mma_tf32(float (&d)[4], const uint32_t (&a)[4],
                                         const uint32_t (&b)[2]) {
    asm volatile(
        "mma.sync.aligned.m16n8k8.row.col.f32.tf32.tf32.f32 "
        "{%0,%1,%2,%3}, {%4,%5,%6,%7}, {%8,%9}, {%0,%1,%2,%3};\n"
        : "+f"(d[0]), "+f"(d[1]), "+f"(d[2]), "+f"(d[3])
        : "r"(a[0]), "r"(a[1]), "r"(a[2]), "r"(a[3]), "r"(b[0]), "r"(b[1]));
}
__device__ __forceinline__ void cp16(uint32_t s, const void* g) {
    asm volatile("cp.async.cg.shared.global [%0], [%1], 16;\n" ::"r"(s), "l"(g));
}
__device__ __forceinline__ void cp_commit() { asm volatile("cp.async.commit_group;\n"); }
__device__ __forceinline__ void cp_wait1() { asm volatile("cp.async.wait_group 1;\n"); }
__device__ __forceinline__ void cp_wait0() { asm volatile("cp.async.wait_group 0;\n"); }

// ================= cache shift (runs on side stream, no consumer) =================
__global__ void shift_caches(const float4* __restrict__ ck,
                             const float4* __restrict__ cv,
                             float4* __restrict__ out) {
    long i = (long)blockIdx.x * 256 + threadIdx.x;
    const long PER = 8L * 4080 * 256;
    if (i < PER) {
        long b = i / (4080L * 256), r = i - b * (4080L * 256);
        out[CK_OFF / 4 + b * 1048576 + r] = ck[b * 1048576 + 4096 + r];
    } else if (i < 2 * PER) {
        long j = i - PER;
        long b = j / (4080L * 256), r = j - b * (4080L * 256);
        out[CV_OFF / 4 + b * 1048576 + r] = cv[b * 1048576 + 4096 + r];
    }
}

// ========== async double-buffered tf32 core: C += A(row,[M][K]) * B(row,[N][K])^T =====
// 256 threads, warps 2x4; A rows = MF*32, B rows = 128, BK = 16.
template <int MF>
__device__ __forceinline__ void gemm_core_async(const float* __restrict__ A, long lda,
                                                const float* __restrict__ B, long ldb,
                                                int ktiles, float* As, float* Bs,
                                                float (&acc)[MF][4][4]) {
    const int tid = threadIdx.x;
    const int lane = tid & 31, wid = tid >> 5;
    const int wm = wid >> 2, wn = wid & 3;
    const int g = lane >> 2, tig = lane & 3;
    const int ASZW = MF * 32 * 20, BSZW = 128 * 20;
    uint32_t asS = (uint32_t)__cvta_generic_to_shared(As);
    uint32_t bsS = (uint32_t)__cvta_generic_to_shared(Bs);

    auto load_tile = [&](int t, int buf) {
        const float* Ak = A + t * 16;
        const float* Bk = B + t * 16;
#pragma unroll
        for (int i = 0; i < MF / 2; i++) {
            int v = tid + i * 256, r = v >> 2, c4 = v & 3;
            cp16(asS + (buf * ASZW + r * 20 + c4 * 4) * 4, Ak + (long)r * lda + c4 * 4);
        }
#pragma unroll
        for (int i = 0; i < 2; i++) {
            int v = tid + i * 256, r = v >> 2, c4 = v & 3;
            cp16(bsS + (buf * BSZW + r * 20 + c4 * 4) * 4, Bk + (long)r * ldb + c4 * 4);
        }
        cp_commit();
    };

    load_tile(0, 0);
    for (int t = 0; t < ktiles; t++) {
        if (t + 1 < ktiles) { load_tile(t + 1, (t + 1) & 1); cp_wait1(); }
        else cp_wait0();
        __syncthreads();
        const float* Af = As + (t & 1) * ASZW;
        const float* Bf = Bs + (t & 1) * BSZW;
#pragma unroll
        for (int ks = 0; ks < 16; ks += 8) {
            uint32_t a[MF][4], b[4][2];
#pragma unroll
            for (int mf = 0; mf < MF; mf++) {
                int m = wm * (MF * 16) + mf * 16;
                a[mf][0] = f2tf(Af[(m + g) * 20 + ks + tig]);
                a[mf][1] = f2tf(Af[(m + g + 8) * 20 + ks + tig]);
                a[mf][2] = f2tf(Af[(m + g) * 20 + ks + tig + 4]);
                a[mf][3] = f2tf(Af[(m + g + 8) * 20 + ks + tig + 4]);
            }
#pragma unroll
            for (int nf = 0; nf < 4; nf++) {
                int n = wn * 32 + nf * 8 + g;
                b[nf][0] = f2tf(Bf[n * 20 + ks + tig]);
                b[nf][1] = f2tf(Bf[n * 20 + ks + tig + 4]);
            }
#pragma unroll
            for (int mf = 0; mf < MF; mf++)
#pragma unroll
                for (int nf = 0; nf < 4; nf++) mma_tf32(acc[mf][nf], a[mf], b[nf]);
        }
        __syncthreads();
    }
}

template <int MF>
__device__ __forceinline__ void store_acc(float* __restrict__ C, long ldc,
                                          float (&acc)[MF][4][4]) {
    const int tid = threadIdx.x;
    const int lane = tid & 31, wid = tid >> 5;
    const int wm = wid >> 2, wn = wid & 3;
    const int g = lane >> 2, tig = lane & 3;
#pragma unroll
    for (int mf = 0; mf < MF; mf++) {
        int m = wm * (MF * 16) + mf * 16 + g;
#pragma unroll
        for (int nf = 0; nf < 4; nf++) {
            int n = wn * 32 + nf * 8 + 2 * tig;
            *(float2*)(C + (long)m * ldc + n) = make_float2(acc[mf][nf][0], acc[mf][nf][1]);
            *(float2*)(C + (long)(m + 8) * ldc + n) = make_float2(acc[mf][nf][2], acc[mf][nf][3]);
        }
    }
}

// ================= QKV projection (split-K=4) =================
__global__ void qkv_gemm_t(const float* __restrict__ X, const float* __restrict__ wq,
                           const float* __restrict__ wk, const float* __restrict__ wv) {
    __shared__ float As[2 * 128 * 20], Bs[2 * 128 * 20];
    int n0 = blockIdx.x * 128, split = blockIdx.y;
    const float* W;
    int nl;
    if (n0 < 4096) { W = wq; nl = n0; }
    else if (n0 < 5120) { W = wk; nl = n0 - 4096; }
    else { W = wv; nl = n0 - 5120; }
    float acc[4][4][4] = {};
    gemm_core_async<4>(X + split * 1024, 4096, W + (long)nl * 4096 + split * 1024, 4096, 64,
                       As, Bs, acc);
    store_acc<4>(g_qkv_part[split] + n0, QKV_N, acc);
}

// ================= RoPE + split reduce + scatter K/V (scratch + out tails) ===========
__global__ void rope_scatter(const float* __restrict__ freqs, float* __restrict__ out) {
    int m = blockIdx.x;
    int b = m >> 4, s = m & 15;
    long base = (long)m * QKV_N;
#pragma unroll 1
    for (int p = threadIdx.x; p < 2048; p += 256) {
        int h = p >> 6, i = p & 63;
        float re = g_qkv_part[0][base + 2 * p] + g_qkv_part[1][base + 2 * p] +
                   g_qkv_part[2][base + 2 * p] + g_qkv_part[3][base + 2 * p];
        float im = g_qkv_part[0][base + 2 * p + 1] + g_qkv_part[1][base + 2 * p + 1] +
                   g_qkv_part[2][base + 2 * p + 1] + g_qkv_part[3][base + 2 * p + 1];
        float c = freqs[(s * 64 + i) * 2], sn = freqs[(s * 64 + i) * 2 + 1];
        long d = ((long)(b * 32 + h) * 16 + s) * 128 + 2 * i;
        g_xq[d] = (re * c - im * sn) * INV_SQRT_HD;
        g_xq[d + 1] = (re * sn + im * c) * INV_SQRT_HD;
    }
    float* cko = out + CK_OFF + (long)b * CACHE_PER_B + (long)(4080 + s) * 1024;
    float* knw = g_knew + (long)(b * 16 + s) * 1024;
#pragma unroll 1
    for (int p = threadIdx.x; p < 512; p += 256) {
        int i = p & 63;
        long o = base + 4096 + 2 * p;
        float re = g_qkv_part[0][o] + g_qkv_part[1][o] + g_qkv_part[2][o] + g_qkv_part[3][o];
        float im = g_qkv_part[0][o + 1] + g_qkv_part[1][o + 1] + g_qkv_part[2][o + 1] +
                   g_qkv_part[3][o + 1];
        float c = freqs[(s * 64 + i) * 2], sn = freqs[(s * 64 + i) * 2 + 1];
        float vr = re * c - im * sn, vi = re * sn + im * c;
        cko[2 * p] = vr; cko[2 * p + 1] = vi;
        knw[2 * p] = vr; knw[2 * p + 1] = vi;
    }
    float* cvo = out + CV_OFF + (long)b * CACHE_PER_B + (long)(4080 + s) * 1024;
    float* vnw = g_vnew + (long)(b * 16 + s) * 1024;
#pragma unroll 1
    for (int j = threadIdx.x; j < 1024; j += 256) {
        long o = base + 5120 + j;
        float v = g_qkv_part[0][o] + g_qkv_part[1][o] + g_qkv_part[2][o] + g_qkv_part[3][o];
        cvo[j] = v; vnw[j] = v;
    }
}

// ================= scores = q @ K^T + mask  (reads ORIGINAL cache at t+16) ==========
__global__ void scores_gemm_t(const float* __restrict__ ck, const float* __restrict__ mask) {
    __shared__ float As[2 * 64 * 20], Bs[2 * 128 * 20];
    int t0 = blockIdx.x * 128, pair = blockIdx.y;
    int b = pair >> 3, kv = pair & 7;
    const int tid = threadIdx.x;
    const int lane = tid & 31, wid = tid >> 5;
    const int wm = wid >> 2, wn = wid & 3;
    const int g = lane >> 2, tig = lane & 3;
    const int ASZW = 64 * 20, BSZW = 128 * 20;
    uint32_t asS = (uint32_t)__cvta_generic_to_shared(As);
    uint32_t bsS = (uint32_t)__cvta_generic_to_shared(Bs);

    // per-thread fixed row sources (rows constant across k-tiles)
    const float* srcA;
    { int r = tid >> 2, c4 = tid & 3;
      srcA = g_xq + (long)pair * 8192 + r * 128 + c4 * 4; }
    const float* srcB[2];
#pragma unroll
    for (int i = 0; i < 2; i++) {
        int v = tid + i * 256, r = v >> 2, c4 = v & 3;
        int tg = t0 + r;
        srcB[i] = (tg < 4080 ? ck + (long)b * CACHE_PER_B + (long)(tg + 16) * 1024
                             : g_knew + (long)(b * 16 + tg - 4080) * 1024) + kv * 128 + c4 * 4;
    }
    auto load_tile = [&](int t, int buf) {
        { int r = tid >> 2, c4 = tid & 3;
          cp16(asS + (buf * ASZW + r * 20 + c4 * 4) * 4, srcA + t * 16); }
#pragma unroll
        for (int i = 0; i < 2; i++) {
            int v = tid + i * 256, r = v >> 2, c4 = v & 3;
            cp16(bsS + (buf * BSZW + r * 20 + c4 * 4) * 4, srcB[i] + t * 16);
        }
        cp_commit();
    };

    float acc[2][4][4] = {};
    load_tile(0, 0);
    for (int t = 0; t < 8; t++) {
        if (t + 1 < 8) { load_tile(t + 1, (t + 1) & 1); cp_wait1(); }
        else cp_wait0();
        __syncthreads();
        const float* Af = As + (t & 1) * ASZW;
        const float* Bf = Bs + (t & 1) * BSZW;
#pragma unroll
        for (int ks = 0; ks < 16; ks += 8) {
            uint32_t a[2][4], bb[4][2];
#pragma unroll
            for (int mf = 0; mf < 2; mf++) {
                int m = wm * 32 + mf * 16;
                a[mf][0] = f2tf(Af[(m + g) * 20 + ks + tig]);
                a[mf][1] = f2tf(Af[(m + g + 8) * 20 + ks + tig]);
                a[mf][2] = f2tf(Af[(m + g) * 20 + ks + tig + 4]);
                a[mf][3] = f2tf(Af[(m + g + 8) * 20 + ks + tig + 4]);
            }
#pragma unroll
            for (int nf = 0; nf < 4; nf++) {
                int n = wn * 32 + nf * 8 + g;
                bb[nf][0] = f2tf(Bf[n * 20 + ks + tig]);
                bb[nf][1] = f2tf(Bf[n * 20 + ks + tig + 4]);
            }
#pragma unroll
            for (int mf = 0; mf < 2; mf++)
#pragma unroll
                for (int nf = 0; nf < 4; nf++) mma_tf32(acc[mf][nf], a[mf], bb[nf]);
        }
        __syncthreads();
    }
#pragma unroll
    for (int mf = 0; mf < 2; mf++) {
        int m = wm * 32 + mf * 16 + g;
#pragma unroll
        for (int nf = 0; nf < 4; nf++) {
            int n = t0 + wn * 32 + nf * 8 + 2 * tig;
            {
                long row = (long)pair * 64 + m; int q = m & 15;
                g_scores[row * 4096 + n]     = acc[mf][nf][0] + mask[q * 4096 + n];
                g_scores[row * 4096 + n + 1] = acc[mf][nf][1] + mask[q * 4096 + n + 1];
            }
            {
                long row = (long)pair * 64 + m + 8; int q = (m + 8) & 15;
                g_scores[row * 4096 + n]     = acc[mf][nf][2] + mask[q * 4096 + n];
                g_scores[row * 4096 + n + 1] = acc[mf][nf][3] + mask[q * 4096 + n + 1];
            }
        }
    }
}

// ================= row softmax over 4096 =================
__global__ void softmax_k() {
    float* row = g_scores + (long)blockIdx.x * 4096;
    int tid = threadIdx.x;
    float v[16];
    float mx = -1e30f;
#pragma unroll
    for (int j = 0; j < 16; j++) {
        v[j] = row[tid + j * 256];
        mx = fmaxf(mx, v[j]);
    }
    __shared__ float red[8];
#pragma unroll
    for (int o = 16; o; o >>= 1) mx = fmaxf(mx, __shfl_xor_sync(0xffffffffu, mx, o));
    if ((tid & 31) == 0) red[tid >> 5] = mx;
    __syncthreads();
    mx = red[0];
#pragma unroll
    for (int i = 1; i < 8; i++) mx = fmaxf(mx, red[i]);
    float s = 0.f;
#pragma unroll
    for (int j = 0; j < 16; j++) { v[j] = __expf(v[j] - mx); s += v[j]; }
#pragma unroll
    for (int o = 16; o; o >>= 1) s += __shfl_xor_sync(0xffffffffu, s, o);
    __syncthreads();
    if ((tid & 31) == 0) red[tid >> 5] = s;
    __syncthreads();
    float tot = 0.f;
#pragma unroll
    for (int i = 0; i < 8; i++) tot += red[i];
    float inv = 1.0f / tot;
#pragma unroll
    for (int j = 0; j < 16; j++) row[tid + j * 256] = v[j] * inv;
}

// ================= attn = probs @ V  (split-K=4; V from original cache at t+16) =====
__global__ void attnv_gemm_t(const float* __restrict__ cv) {
    __shared__ float As[2 * 64 * 20], Vs[2 * 16 * 136];
    int pair = blockIdx.x, split = blockIdx.y;
    int b = pair >> 3, kvv = pair & 7;
    const int tid = threadIdx.x;
    const int lane = tid & 31, wid = tid >> 5;
    const int wm = wid >> 2, wn = wid & 3;
    const int g = lane >> 2, tig = lane & 3;
    const int ASZW = 64 * 20, VSZW = 16 * 136;
    uint32_t asS = (uint32_t)__cvta_generic_to_shared(As);
    uint32_t vsS = (uint32_t)__cvta_generic_to_shared(Vs);
    const float* A = g_scores + (long)pair * 64 * 4096 + split * 1024;
    int k0 = split * 1024;

    auto load_tile = [&](int t, int buf) {
        { int r = tid >> 2, c4 = tid & 3;
          cp16(asS + (buf * ASZW + r * 20 + c4 * 4) * 4, A + (long)r * 4096 + t * 16 + c4 * 4); }
#pragma unroll
        for (int i = 0; i < 2; i++) {
            int v = tid + i * 256;
            int kk = v >> 5, n4 = v & 31;
            int tg = k0 + t * 16 + kk;
            const float* src =
                (tg < 4080 ? cv + (long)b * CACHE_PER_B + (long)(tg + 16) * 1024
                           : g_vnew + (long)(b * 16 + tg - 4080) * 1024) + kvv * 128 + n4 * 4;
            cp16(vsS + (buf * VSZW + kk * 136 + n4 * 4) * 4, src);
        }
        cp_commit();
    };

    float acc[2][4][4] = {};
    load_tile(0, 0);
    for (int t = 0; t < 64; t++) {
        if (t + 1 < 64) { load_tile(t + 1, (t + 1) & 1); cp_wait1(); }
        else cp_wait0();
        __syncthreads();
        const float* Af = As + (t & 1) * ASZW;
        const float* Vf = Vs + (t & 1) * VSZW;
#pragma unroll
        for (int ks = 0; ks < 16; ks += 8) {
            uint32_t a[2][4], bb[4][2];
#pragma unroll
            for (int mf = 0; mf < 2; mf++) {
                int m = wm * 32 + mf * 16;
                a[mf][0] = f2tf(Af[(m + g) * 20 + ks + tig]);
                a[mf][1] = f2tf(Af[(m + g + 8) * 20 + ks + tig]);
                a[mf][2] = f2tf(Af[(m + g) * 20 + ks + tig + 4]);
                a[mf][3] = f2tf(Af[(m + g + 8) * 20 + ks + tig + 4]);
            }
#pragma unroll
            for (int nf = 0; nf < 4; nf++) {
                int n = wn * 32 + nf * 8 + g;
                bb[nf][0] = f2tf(Vf[(ks + tig) * 136 + n]);
                bb[nf][1] = f2tf(Vf[(ks + tig + 4) * 136 + n]);
            }
#pragma unroll
            for (int mf = 0; mf < 2; mf++)
#pragma unroll
                for (int nf = 0; nf < 4; nf++) mma_tf32(acc[mf][nf], a[mf], bb[nf]);
        }
        __syncthreads();
    }
    store_acc<2>(g_attn_part[split] + (long)pair * 64 * 128, 128, acc);
}

__global__ void attnv_reduce() {
    long idx = (long)blockIdx.x * 256 + threadIdx.x;  // float4 index
    long o = idx * 4;
    float4 p0 = ((const float4*)g_attn_part[0])[idx];
    float4 p1 = ((const float4*)g_attn_part[1])[idx];
    float4 p2 = ((const float4*)g_attn_part[2])[idx];
    float4 p3 = ((const float4*)g_attn_part[3])[idx];
    float4 s = make_float4(p0.x + p1.x + p2.x + p3.x, p0.y + p1.y + p2.y + p3.y,
                           p0.z + p1.z + p2.z + p3.z, p0.w + p1.w + p2.w + p3.w);
    int pair = (int)(o >> 13), r = (int)((o >> 7) & 63), d = (int)(o & 127);
    int b = pair >> 3, kv = pair & 7, hp = r >> 4, q = r & 15;
    *(float4*)(g_attn + ((long)(b * 16 + q) * 4096 + (kv * 4 + hp) * 128 + d)) = s;
}

// ================= out = attn @ wo^T (split-K=4) =================
__global__ void out_gemm_t(const float* __restrict__ wo) {
    __shared__ float As[2 * 128 * 20], Bs[2 * 128 * 20];
    int n0 = blockIdx.x * 128, split = blockIdx.y;
    float acc[4][4][4] = {};
    gemm_core_async<4>(g_attn + split * 1024, 4096, wo + (long)n0 * 4096 + split * 1024, 4096,
                       64, As, Bs, acc);
    store_acc<4>(g_out_part[split] + n0, 4096, acc);
}

__global__ void out_reduce(float* __restrict__ out) {
    long idx = (long)blockIdx.x * 256 + threadIdx.x;
    float4 p0 = ((const float4*)g_out_part[0])[idx];
    float4 p1 = ((const float4*)g_out_part[1])[idx];
    float4 p2 = ((const float4*)g_out_part[2])[idx];
    float4 p3 = ((const float4*)g_out_part[3])[idx];
    ((float4*)out)[idx] = make_float4(p0.x + p1.x + p2.x + p3.x, p0.y + p1.y + p2.y + p3.y,
                                      p0.z + p1.z + p2.z + p3.z, p0.w + p1.w + p2.w + p3.w);
}

// ================= launch =================
extern "C" void kernel_launch(void* const* d_in, const int* in_sizes, int n_in,
                              void* d_out, int out_size) {
    const float* x     = (const float*)d_in[0];
    const float* mask  = (const float*)d_in[1];
    const float* freqs = (const float*)d_in[2];
    const float* ck    = (const float*)d_in[3];
    const float* cv    = (const float*)d_in[4];
    const float* wq    = (const float*)d_in[5];
    const float* wk    = (const float*)d_in[6];
    const float* wv    = (const float*)d_in[7];
    const float* wo    = (const float*)d_in[8];
    float* out = (float*)d_out;

    // one-time side-stream setup (host objects only; no device memory)
    static cudaStream_t s_copy = nullptr;
    static cudaEvent_t ev_fork = nullptr, ev_join = nullptr;
    if (!s_copy) {
        cudaStreamCreateWithFlags(&s_copy, cudaStreamNonBlocking);
        cudaEventCreateWithFlags(&ev_fork, cudaEventDisableTiming);
        cudaEventCreateWithFlags(&ev_join, cudaEventDisableTiming);
    }

    // fork: cache shift overlaps all compute (nothing downstream reads shifted copy)
    cudaEventRecord(ev_fork, 0);
    cudaStreamWaitEvent(s_copy, ev_fork, 0);
    shift_caches<<<65280, 256, 0, s_copy>>>((const float4*)ck, (const float4*)cv,
                                            (float4*)out);
    cudaEventRecord(ev_join, s_copy);

    // compute chain on main stream, reading ORIGINAL caches
    qkv_gemm_t<<<dim3(48, 4), 256>>>(x, wq, wk, wv);
    rope_scatter<<<128, 256>>>(freqs, out);
    scores_gemm_t<<<dim3(32, 64), 256>>>(ck, mask);
    softmax_k<<<4096, 256>>>();
    attnv_gemm_t<<<dim3(64, 4), 256>>>(cv);
    attnv_reduce<<<512, 256>>>();
    out_gemm_t<<<dim3(32, 4), 256>>>(wo);
    out_reduce<<<512, 256>>>(out);

    // join: shift must complete before harness observes d_out
    cudaStreamWaitEvent(0, ev_join, 0);
}